// round 15
// baseline (speedup 1.0000x reference)
#include <cuda_runtime.h>

#define AA 8192
#define BB 8192
#define KK 10
#define NBLK 444          // 3 CTAs/SM on 148 SMs (<=3/SM on 152) -> single wave
#define RPT 16            // rows per tile
#define NTILE 8192        // 16 col-chunks (512 cols) x 512 row-tiles (16 rows)
#define MAXSLOTS 20       // max tiles per block (ceil(8192/444)=19) + 1

// Scratch (no allocations allowed).
__device__ float d_bsum[NBLK];
__device__ unsigned int d_count = 0;

// ---------------- packed f32x2 helpers ----------------
__device__ __forceinline__ unsigned long long f2pk(float lo, float hi) {
    unsigned long long r;
    asm("mov.b64 %0, {%1, %2};" : "=l"(r) : "f"(lo), "f"(hi));
    return r;
}
__device__ __forceinline__ unsigned long long f2fma(unsigned long long a, unsigned long long b,
                                                    unsigned long long c) {
    unsigned long long d;
    asm("fma.rn.f32x2 %0, %1, %2, %3;" : "=l"(d) : "l"(a), "l"(b), "l"(c));
    return d;
}
__device__ __forceinline__ unsigned long long f2mul(unsigned long long a, unsigned long long b) {
    unsigned long long d;
    asm("mul.rn.f32x2 %0, %1, %2;" : "=l"(d) : "l"(a), "l"(b));
    return d;
}
__device__ __forceinline__ float f2sum(unsigned long long a) {
    float lo, hi;
    asm("mov.b64 {%0, %1}, %2;" : "=f"(lo), "=f"(hi) : "l"(a));
    return lo + hi;
}
__device__ __forceinline__ float f2lo(unsigned long long a) {
    float lo, hi;
    asm("mov.b64 {%0, %1}, %2;" : "=f"(lo), "=f"(hi) : "l"(a));
    return lo;
}

// ---------------- per-row fold: 2 columns/lane, k-pair math, coeffs from SMEM ----------------
__device__ __forceinline__ void row_accum(float2 w, const ulonglong2* __restrict__ cs,
                                          const unsigned long long (*prkp)[5],
                                          unsigned long long& t0, unsigned long long& t1,
                                          unsigned long long& t2, unsigned long long& t3,
                                          unsigned long long& t4, float& tots) {
    ulonglong2 L0 = cs[0];   // (c0,c1)(c2,c3)
    ulonglong2 L1 = cs[1];   // (c4,c5)(c6,c7)
    ulonglong2 L2 = cs[2];   // (c8,c9)(s, 0)

    unsigned long long wd0 = f2pk(w.x, w.x);
    unsigned long long wd1 = f2pk(w.y, w.y);
    unsigned long long acc;

    acc = f2fma(wd1, prkp[1][0], f2mul(wd0, prkp[0][0]));  t0 = f2fma(acc, L0.x, t0);
    acc = f2fma(wd1, prkp[1][1], f2mul(wd0, prkp[0][1]));  t1 = f2fma(acc, L0.y, t1);
    acc = f2fma(wd1, prkp[1][2], f2mul(wd0, prkp[0][2]));  t2 = f2fma(acc, L1.x, t2);
    acc = f2fma(wd1, prkp[1][3], f2mul(wd0, prkp[0][3]));  t3 = f2fma(acc, L1.y, t3);
    acc = f2fma(wd1, prkp[1][4], f2mul(wd0, prkp[0][4]));  t4 = f2fma(acc, L2.x, t4);

    tots = fmaf(w.x + w.y, f2lo(L2.y), tots);
}

// ---------------- single fused kernel ----------------
__global__ __launch_bounds__(256, 3)
void prcut_fused(const float* __restrict__ W, const float* __restrict__ Pl,
                 const float* __restrict__ Pr, const float* __restrict__ cp,
                 float* __restrict__ out) {
    // cs_sm[slot][row][6] u64 pairs: (c0,c1)..(c8,c9),(s,0). 48B/row.
    __shared__ unsigned long long cs_sm[MAXSLOTS * RPT * 6];   // 15.4 KB
    __shared__ float sred[8];
    __shared__ int is_last;

    const int b   = blockIdx.x;
    const int tB0 = (int)(((long long)b * NTILE) / NBLK);
    const int tB1 = (int)(((long long)(b + 1) * NTILE) / NBLK);
    const int nslots = tB1 - tB0;

    // ---- stage fold coefficients for this block's tiles ----
    for (int i = threadIdx.x; i < nslots * RPT; i += 256) {
        const int slot = i >> 4;          // / RPT
        const int row  = i & (RPT - 1);
        const int rowTile = (tB0 + slot) & 511;
        const int a = rowTile * RPT + row;
        float inv[KK];
#pragma unroll
        for (int k = 0; k < KK; k++) inv[k] = 1.0f / __ldg(&cp[k]);
        const float2* plrow = reinterpret_cast<const float2*>(Pl + (size_t)a * KK);
        unsigned long long* dst = &cs_sm[(size_t)i * 6];
        float s = 0.0f;
#pragma unroll
        for (int j = 0; j < 5; j++) {
            float2 p = __ldg(&plrow[j]);
            float c0 = (1.0f - 2.0f * p.x) * inv[2 * j];
            float c1 = (1.0f - 2.0f * p.y) * inv[2 * j + 1];
            dst[j] = f2pk(c0, c1);
            s = fmaf(p.x, inv[2 * j], s);
            s = fmaf(p.y, inv[2 * j + 1], s);
        }
        dst[5] = f2pk(s, 0.0f);
    }
    __syncthreads();

    // ---- main pass over W ----
    unsigned long long prkp[2][5];   // prkp[c][j] = (P_r[b_c,2j], P_r[b_c,2j+1])
    int cc = -1;
    unsigned long long t0 = 0ull, t1 = 0ull, t2 = 0ull, t3 = 0ull, t4 = 0ull;
    float tots = 0.0f;
    const float2* W2 = reinterpret_cast<const float2*>(W);

    for (int t = tB0; t < tB1; t++) {
        const int colChunk = t >> 9;       // 0..15 (512 cols each)
        const int rowTile  = t & 511;      // 0..511 (16 rows each)
        const int slot     = t - tB0;

        if (colChunk != cc) {              // <=1 crossing per block
            cc = colChunk;
            const int col = colChunk * 512 + threadIdx.x * 2;
#pragma unroll
            for (int c = 0; c < 2; c++) {
                const float2* prow = reinterpret_cast<const float2*>(Pr + (size_t)(col + c) * KK);
#pragma unroll
                for (int j = 0; j < 5; j++) {
                    float2 p = __ldg(&prow[j]);
                    prkp[c][j] = f2pk(p.x, p.y);
                }
            }
        }

        const float2* wp = W2 + (size_t)(rowTile * RPT) * (BB / 2) + colChunk * 256 + threadIdx.x;
        const ulonglong2* csbase = reinterpret_cast<const ulonglong2*>(&cs_sm[(size_t)slot * RPT * 6]);

#pragma unroll 1
        for (int r = 0; r < RPT; r += 8) {
            // 8 independent W row loads: 2 KB in flight per warp
            float2 w0 = __ldg(wp + 0 * (BB / 2));
            float2 w1 = __ldg(wp + 1 * (BB / 2));
            float2 w2 = __ldg(wp + 2 * (BB / 2));
            float2 w3 = __ldg(wp + 3 * (BB / 2));
            float2 w4 = __ldg(wp + 4 * (BB / 2));
            float2 w5 = __ldg(wp + 5 * (BB / 2));
            float2 w6 = __ldg(wp + 6 * (BB / 2));
            float2 w7 = __ldg(wp + 7 * (BB / 2));
            wp += 8 * (BB / 2);
            const ulonglong2* csr = csbase + r * 3;
            row_accum(w0, csr + 0 * 3, prkp, t0, t1, t2, t3, t4, tots);
            row_accum(w1, csr + 1 * 3, prkp, t0, t1, t2, t3, t4, tots);
            row_accum(w2, csr + 2 * 3, prkp, t0, t1, t2, t3, t4, tots);
            row_accum(w3, csr + 3 * 3, prkp, t0, t1, t2, t3, t4, tots);
            row_accum(w4, csr + 4 * 3, prkp, t0, t1, t2, t3, t4, tots);
            row_accum(w5, csr + 5 * 3, prkp, t0, t1, t2, t3, t4, tots);
            row_accum(w6, csr + 6 * 3, prkp, t0, t1, t2, t3, t4, tots);
            row_accum(w7, csr + 7 * 3, prkp, t0, t1, t2, t3, t4, tots);
        }
    }

    // ---- block reduction ----
    float tv = tots + f2sum(t0) + f2sum(t1) + f2sum(t2) + f2sum(t3) + f2sum(t4);
#pragma unroll
    for (int off = 16; off > 0; off >>= 1)
        tv += __shfl_xor_sync(0xFFFFFFFFu, tv, off);

    const int wid = threadIdx.x >> 5;
    const int lid = threadIdx.x & 31;
    if (lid == 0) sred[wid] = tv;
    __syncthreads();
    if (threadIdx.x == 0) {
        float s = 0.0f;
#pragma unroll
        for (int i = 0; i < 8; i++) s += sred[i];
        d_bsum[b] = s;
        __threadfence();
        unsigned int old = atomicAdd(&d_count, 1u);
        is_last = (old == NBLK - 1) ? 1 : 0;
    }
    __syncthreads();

    // ---- last block: deterministic final reduction + counter reset for graph replay ----
    if (is_last) {
        __threadfence();
        __shared__ float fin[256];
        const int tdx = threadIdx.x;
        float v = 0.0f;
        if (tdx < NBLK) v = *((volatile float*)&d_bsum[tdx]);
        if (tdx + 256 < NBLK) v += *((volatile float*)&d_bsum[tdx + 256]);
        fin[tdx] = v;
        __syncthreads();
#pragma unroll
        for (int off = 128; off > 0; off >>= 1) {
            if (tdx < off) fin[tdx] += fin[tdx + off];
            __syncthreads();
        }
        if (tdx == 0) {
            d_count = 0;   // reset for next graph replay (only last block writes)
            out[0] = fin[0];
        }
    }
}

extern "C" void kernel_launch(void* const* d_in, const int* in_sizes, int n_in,
                              void* d_out, int out_size) {
    const float* W  = (const float*)d_in[0];
    const float* Pl = (const float*)d_in[1];
    const float* Pr = (const float*)d_in[2];
    const float* cp = (const float*)d_in[3];
    float* out = (float*)d_out;

    prcut_fused<<<NBLK, 256>>>(W, Pl, Pr, cp, out);
}